// round 13
// baseline (speedup 1.0000x reference)
#include <cuda_runtime.h>
#include <cuda_fp16.h>

#define DIMN   200
#define LEN    256
#define BATCH  8
#define NTOK   (BATCH*LEN)      // 2048
#define D2     (2*DIMN)         // 400
#define NBLK   296              // persistent blocks; 2/SM guaranteed resident (<=148*2)

// ---------------- scratch (static device memory; no allocations) ----------------
__device__ float  g_h    [NTOK*DIMN + 64];
__device__ float  g_h1m  [NTOK*DIMN + 64];
__device__ float2 g_hpack[NTOK*DIMN + 64];
__device__ float  g_hf2c [NTOK*DIMN];
__device__ float  g_sfw  [NTOK*DIMN];
__device__ float  g_sbw  [NTOK*DIMN];
__device__ float  g_hsumP[64*DIMN + 64];
__device__ float  g_uu   [NTOK*D2];
__device__ float  g_tmp  [NTOK*D2];
__device__ float  g_part2[64*D2];
__device__ int    g_arrivals;

__device__ __forceinline__ float eluf(float a){ return a > 0.0f ? a : expm1f(a); }
__device__ __forceinline__ __half2 hw_tanh2(__half2 x){
    __half2 y; asm("tanh.approx.f16x2 %0, %1;" : "=r"(*(unsigned*)&y) : "r"(*(unsigned*)&x)); return y;
}
__device__ __forceinline__ __half2 hw_ex22(__half2 x){
    __half2 y; asm("ex2.approx.f16x2 %0, %1;" : "=r"(*(unsigned*)&y) : "r"(*(unsigned*)&x)); return y;
}
__device__ __forceinline__ unsigned long long pk2(float lo, float hi){
    unsigned long long r; asm("mov.b64 %0, {%1,%2};" : "=l"(r) : "f"(lo), "f"(hi)); return r;
}
__device__ __forceinline__ void fma2(unsigned long long& c, unsigned long long a, unsigned long long b){
    asm("fma.rn.f32x2 %0, %1, %2, %0;" : "+l"(c) : "l"(a), "l"(b));
}
__device__ __forceinline__ void unpk2(float& lo, float& hi, unsigned long long v){
    asm("mov.b64 {%0,%1}, %2;" : "=f"(lo), "=f"(hi) : "l"(v));
}

// global phase barrier: every block arrives once; spin until all NBLK arrived k times
__device__ __forceinline__ void gbar(int target) {
    __syncthreads();
    __threadfence();
    if (threadIdx.x == 0) {
        atomicAdd(&g_arrivals, 1);
        while (*((volatile int*)&g_arrivals) < target) { }
        __threadfence();
    }
    __syncthreads();
}

// 128-thread named barrier for a half-block worker
__device__ __forceinline__ void barh(int half) {
    asm volatile("bar.sync %0, %1;" :: "r"(half + 1), "r"(128) : "memory");
}

#define BM 32
#define BN 64
#define BK 16

// ==== GEMM worker body: 128 threads (one half-block), single-buffered smem,
//      FFMA2 4x4 microtile. Identical math to the validated R12 kernel. ====
template<int MODE, int K, int N>
__device__ void gemm_body(
    int ltid, int half, int bx, int by, int dir,
    float (*As_)[BM], float (*Bs_)[BN], float (*red_)[BN],
    const float* __restrict__ A,
    const float* __restrict__ B0, const float* __restrict__ B1, const float* __restrict__ B2,
    const float* __restrict__ bias0, const float* __restrict__ bias2,
    const int* __restrict__ xidx, const float* __restrict__ emb,
    const float* __restrict__ cptr)
{
    const int t0 = bx * BM;

    // ---- hsum side-channel slice (MODE 1, by==12); no barriers used ----
    if (MODE == 1 && by == 12) {
        for (int e = ltid; e < DIMN; e += 128) {
            float s = 0.0f;
            #pragma unroll 4
            for (int j = 0; j < BM; ++j) s += g_h[(t0 + j)*DIMN + e];
            g_hsumP[bx*DIMN + e] = s;
        }
        return;
    }

    const int tx = ltid & 15;
    const int ty = ltid >> 4;

    int n0, matid = 0;
    const float* B = B0;
    if (MODE == 1) {
        matid = by >> 2;
        n0 = (by & 3) * BN;
        B  = (matid == 0) ? B0 : (matid == 1) ? B1 : B2;
    } else {
        n0 = by * BN;
    }

    const float* Asrc;
    if      (MODE == 0) Asrc = A;
    else if (MODE == 1) Asrc = g_h;
    else if (MODE == 2) Asrc = dir ? g_sbw : g_sfw;
    else if (MODE == 3) Asrc = g_uu;
    else                Asrc = g_tmp;

    const int am = ltid >> 2;           // 0..31
    const int ak = (ltid & 3) * 4;      // 0,4,8,12
    const int bk = ltid >> 4;           // 0..7 (+8)
    const int bn = (ltid & 15) * 4;     // 0..60

    long arow;
    if (MODE == 0) arow = (long)__ldg(&xidx[t0 + am]) * K;
    else           arow = (long)(t0 + am) * K;

    const int gn_b = n0 + bn;
    const bool bvalid = (gn_b < N);

    unsigned long long acc2[4][2];
    #pragma unroll
    for (int i = 0; i < 4; i++) { acc2[i][0] = 0ULL; acc2[i][1] = 0ULL; }

    float4 av, bv0, bv1;
    auto loadTile = [&](int k0) {
        int kq = k0 + ak;
        av = make_float4(0,0,0,0);
        if (K % BK == 0 || kq < K)
            av = *reinterpret_cast<const float4*>(Asrc + arow + kq);
        int k1 = k0 + bk, k2 = k0 + bk + 8;
        bv0 = make_float4(0,0,0,0);
        bv1 = make_float4(0,0,0,0);
        if (bvalid) {
            if (K % BK == 0 || k1 < K) bv0 = *reinterpret_cast<const float4*>(B + (long)k1 * N + gn_b);
            if (K % BK == 0 || k2 < K) bv1 = *reinterpret_cast<const float4*>(B + (long)k2 * N + gn_b);
        }
    };

    loadTile(0);
    for (int k0 = 0; k0 < K; k0 += BK) {
        As_[ak+0][am]=av.x; As_[ak+1][am]=av.y; As_[ak+2][am]=av.z; As_[ak+3][am]=av.w;
        *reinterpret_cast<float4*>(&Bs_[bk  ][bn]) = bv0;
        *reinterpret_cast<float4*>(&Bs_[bk+8][bn]) = bv1;
        barh(half);

        const bool more = (k0 + BK < K);
        if (more) loadTile(k0 + BK);

        #pragma unroll
        for (int kk = 0; kk < BK; kk++) {
            float4 a4 = *reinterpret_cast<const float4*>(&As_[kk][ty*4]);
            float4 b4 = *reinterpret_cast<const float4*>(&Bs_[kk][tx*4]);
            unsigned long long b01 = pk2(b4.x, b4.y);
            unsigned long long b23 = pk2(b4.z, b4.w);
            float aa[4] = {a4.x, a4.y, a4.z, a4.w};
            #pragma unroll
            for (int i = 0; i < 4; i++) {
                unsigned long long ai = pk2(aa[i], aa[i]);
                fma2(acc2[i][0], ai, b01);
                fma2(acc2[i][1], ai, b23);
            }
        }
        barh(half);
    }

    float acc[4][4];
    #pragma unroll
    for (int i = 0; i < 4; i++) {
        unpk2(acc[i][0], acc[i][1], acc2[i][0]);
        unpk2(acc[i][2], acc[i][3], acc2[i][1]);
    }

    // ---------------- epilogues (logic identical to validated version) ----------
    int  gcv[4]; bool ok[4]; float bj[4];
    #pragma unroll
    for (int j = 0; j < 4; j++) {
        gcv[j] = n0 + tx*4 + j;
        ok[j]  = gcv[j] < N;
    }

    if (MODE == 0) {
        #pragma unroll
        for (int j = 0; j < 4; j++) bj[j] = ok[j] ? __ldg(&bias0[gcv[j]]) : 0.0f;
        #pragma unroll
        for (int i = 0; i < 4; i++) {
            int gt = t0 + ty*4 + i;
            #pragma unroll
            for (int j = 0; j < 4; j++)
                if (ok[j]) g_h[gt*DIMN + gcv[j]] = eluf(acc[i][j] + bj[j]);
        }
    }
    else if (MODE == 1) {
        const float invc = 1.0f / __ldg(cptr);
        #pragma unroll
        for (int j = 0; j < 4; j++) {
            bj[j] = 0.0f;
            if (ok[j]) {
                if (matid == 0) bj[j] = __ldg(&bias0[gcv[j]]);
                if (matid == 2) bj[j] = __ldg(&bias2[gcv[j]]);
            }
        }
        #pragma unroll
        for (int i = 0; i < 4; i++) {
            int gt = t0 + ty*4 + i;
            long eoff = (long)__ldg(&xidx[gt]) * DIMN;
            #pragma unroll
            for (int j = 0; j < 4; j++) {
                if (!ok[j]) continue;
                if (matid == 0) {
                    bool mk = (__ldg(&emb[eoff + gcv[j]]) == 1.0f);
                    g_h1m[gt*DIMN + gcv[j]] = mk ? 1e30f : (acc[i][j] + bj[j]) * invc;
                } else if (matid == 1) {
                    bool mk = (__ldg(&emb[eoff + gcv[j]]) == 1.0f);
                    float2 pp;
                    pp.x = mk ? 1e30f : acc[i][j] * invc;
                    pp.y = g_h[gt*DIMN + gcv[j]];
                    g_hpack[gt*DIMN + gcv[j]] = pp;
                } else {
                    g_hf2c[gt*DIMN + gcv[j]] = acc[i][j] + bj[j];
                }
            }
        }
    }
    else if (MODE == 2) {
        #pragma unroll
        for (int i = 0; i < 4; i++) {
            int gt = t0 + ty*4 + i;
            #pragma unroll
            for (int j = 0; j < 4; j++) {
                if (!ok[j]) continue;
                int idx = gt*DIMN + gcv[j];
                float f = 1.0f / (1.0f + __expf(-(acc[i][j] + g_hf2c[idx])));
                float hh = g_h[idx];
                float ss = Asrc[idx];
                g_uu[gt*D2 + dir*DIMN + gcv[j]] = f*hh + (1.0f - f)*ss;
            }
        }
    }
    else if (MODE == 3) {
        #pragma unroll
        for (int j = 0; j < 4; j++) bj[j] = ok[j] ? __ldg(&bias0[gcv[j]]) : 0.0f;
        #pragma unroll
        for (int i = 0; i < 4; i++) {
            int gt = t0 + ty*4 + i;
            #pragma unroll
            for (int j = 0; j < 4; j++)
                if (ok[j]) g_tmp[gt*D2 + gcv[j]] = eluf(acc[i][j] + bj[j]);
        }
    }
    else { // MODE 4
        #pragma unroll
        for (int j = 0; j < 4; j++) bj[j] = ok[j] ? __ldg(&bias0[gcv[j]]) : 0.0f;
        float pr[4] = {0,0,0,0};
        #pragma unroll
        for (int i = 0; i < 4; i++) {
            int gt = t0 + ty*4 + i;
            #pragma unroll
            for (int j = 0; j < 4; j++) {
                if (!ok[j]) continue;
                float att = acc[i][j] + bj[j];
                pr[j] += g_uu[gt*D2 + gcv[j]] * att;
            }
        }
        barh(half);
        #pragma unroll
        for (int j = 0; j < 4; j++) red_[ty][tx*4 + j] = pr[j];
        barh(half);
        if (ltid < BN) {
            float s = 0.0f;
            #pragma unroll
            for (int r = 0; r < 8; r++) s += red_[r][ltid];
            int gc = n0 + ltid;
            if (gc < N) g_part2[bx*D2 + gc] = s;
        }
        barh(half);   // protect red_ before next job reuses it
    }
}

// ==== attention body (block-wide; threads 224..255 idle; no barriers) ====
__device__ void attn_body(int lx, int b, const float* __restrict__ cptr)
{
    const int e = threadIdx.x;
    if (e >= 224) return;
    const int l0 = lx * 4;

    const float C  = __ldg(cptr);
    const float ktf = C * 1.4426950408889634f;
    const __half2 kt2 = __float2half2_rn(ktf);

    float h1s[4];
    #pragma unroll
    for (int i = 0; i < 4; i++) h1s[i] = g_h1m[(b*LEN + l0 + i)*DIMN + e];

    float denf[4] = {0,0,0,0}, numf[4] = {0,0,0,0};
    float denb[4] = {0,0,0,0}, numb[4] = {0,0,0,0};

    const float2* __restrict__ hp = g_hpack + (size_t)b*LEN*DIMN + e;

    #pragma unroll 2
    for (int m = 0; m < l0; ++m) {
        float2 pv = __ldg(hp + m*DIMN);
        float zc[4];
        #pragma unroll
        for (int i = 0; i < 4; i++) zc[i] = h1s[i] + pv.x;
        __half2 wa = hw_ex22(__hmul2(hw_tanh2(__floats2half2_rn(zc[0], zc[1])), kt2));
        __half2 wb = hw_ex22(__hmul2(hw_tanh2(__floats2half2_rn(zc[2], zc[3])), kt2));
        float2 w01 = __half22float2(wa), w23 = __half22float2(wb);
        float w[4] = {w01.x, w01.y, w23.x, w23.y};
        #pragma unroll
        for (int i = 0; i < 4; i++) {
            float wi = (zc[i] < 1e29f) ? w[i] : 0.0f;
            denb[i] += wi;
            numb[i] = fmaf(wi, pv.y, numb[i]);
        }
    }
    #pragma unroll
    for (int i2 = 0; i2 < 4; i2++) {
        float2 pv = __ldg(hp + (l0 + i2)*DIMN);
        float zc[4];
        #pragma unroll
        for (int i = 0; i < 4; i++) zc[i] = h1s[i] + pv.x;
        __half2 wa = hw_ex22(__hmul2(hw_tanh2(__floats2half2_rn(zc[0], zc[1])), kt2));
        __half2 wb = hw_ex22(__hmul2(hw_tanh2(__floats2half2_rn(zc[2], zc[3])), kt2));
        float2 w01 = __half22float2(wa), w23 = __half22float2(wb);
        float w[4] = {w01.x, w01.y, w23.x, w23.y};
        #pragma unroll
        for (int i = 0; i < 4; i++) {
            if (i == i2) continue;
            float wi = (zc[i] < 1e29f) ? w[i] : 0.0f;
            if (i < i2) { denf[i] += wi; numf[i] = fmaf(wi, pv.y, numf[i]); }
            else        { denb[i] += wi; numb[i] = fmaf(wi, pv.y, numb[i]); }
        }
    }
    #pragma unroll 2
    for (int m = l0 + 4; m < LEN; ++m) {
        float2 pv = __ldg(hp + m*DIMN);
        float zc[4];
        #pragma unroll
        for (int i = 0; i < 4; i++) zc[i] = h1s[i] + pv.x;
        __half2 wa = hw_ex22(__hmul2(hw_tanh2(__floats2half2_rn(zc[0], zc[1])), kt2));
        __half2 wb = hw_ex22(__hmul2(hw_tanh2(__floats2half2_rn(zc[2], zc[3])), kt2));
        float2 w01 = __half22float2(wa), w23 = __half22float2(wb);
        float w[4] = {w01.x, w01.y, w23.x, w23.y};
        #pragma unroll
        for (int i = 0; i < 4; i++) {
            float wi = (zc[i] < 1e29f) ? w[i] : 0.0f;
            denf[i] += wi;
            numf[i] = fmaf(wi, pv.y, numf[i]);
        }
    }

    if (e < DIMN) {
        float hs = 0.0f;
        #pragma unroll
        for (int t = 0; t < 8; t++) hs += g_hsumP[(b*8 + t)*DIMN + e];
        hs *= 0.00390625f;
        #pragma unroll
        for (int i = 0; i < 4; i++) {
            int idx = (b*LEN + l0 + i)*DIMN + e;
            g_sfw[idx] = (denf[i] > 0.0f) ? __fdividef(numf[i], denf[i]) : hs;
            g_sbw[idx] = (denb[i] > 0.0f) ? __fdividef(numb[i], denb[i]) : hs;
        }
    }
}

// ==== final body (block-wide, blocks 0..7) ====
__device__ void final_body(int b, float* ss, float* red2,
    const float* __restrict__ F1_w, const float* __restrict__ F1_b,
    const float* __restrict__ F2_w, const float* __restrict__ F2_b,
    float* __restrict__ out)
{
    const int tid = threadIdx.x;
    for (int e = tid; e < D2; e += 256) {
        float s = 0.0f;
        #pragma unroll
        for (int mt = 0; mt < 8; ++mt)
            s += g_part2[(b*8 + mt)*D2 + e];
        ss[e] = s;
    }
    __syncthreads();

    float v = 0.0f;
    if (tid < DIMN) {
        float acc = F1_b[tid];
        #pragma unroll 4
        for (int k = 0; k < D2; ++k)
            acc = fmaf(ss[k], F1_w[k*DIMN + tid], acc);
        acc = fmaxf(acc, 0.0f);
        v = acc * F2_w[tid];
    }
    red2[tid] = v;
    __syncthreads();
    for (int s = 128; s > 0; s >>= 1) {
        if (tid < s) red2[tid] += red2[tid + s];
        __syncthreads();
    }
    if (tid == 0) out[b] = red2[0] + F2_b[0];
}

// ======================= persistent mega-kernel =======================
__global__ void reset_kernel() { g_arrivals = 0; }

__global__ void __launch_bounds__(256, 2) mega_kernel(
    const int* x, const float* emb,
    const float* Wh_w, const float* Wh_b,
    const float* W1_w, const float* W2_w, const float* batt, const float* cptr,
    const float* Wf1_w, const float* Wf2_w, const float* Wf2_b,
    const float* Ws1_w, const float* Ws1_b, const float* Ws_w, const float* Ws_b,
    const float* F1_w, const float* F1_b, const float* F2_w, const float* F2_b,
    float* out)
{
    __shared__ __align__(16) float sAs[2][BK][BM];
    __shared__ __align__(16) float sBs[2][BK][BN];
    __shared__ __align__(16) float sred[2][8][BN];
    __shared__ float sss[D2];
    __shared__ float sred2[256];

    const int bid  = blockIdx.x;
    const int tid  = threadIdx.x;
    const int half = tid >> 7;
    const int ltid = tid & 127;
    const int wkr  = bid*2 + half;       // 0..591

    float (*As_)[BM] = sAs[half];
    float (*Bs_)[BN] = sBs[half];
    float (*rd_)[BN] = sred[half];

    // P0: G1  (256 jobs)
    for (int j = wkr; j < 256; j += 2*NBLK)
        gemm_body<0,DIMN,DIMN>(ltid, half, j % 64, j / 64, 0, As_, Bs_, rd_,
                               emb, Wh_w, nullptr, nullptr, Wh_b, nullptr, x, emb, cptr);
    gbar(NBLK*1);

    // P1: G2  (832 jobs: 64 x 13)
    for (int j = wkr; j < 832; j += 2*NBLK)
        gemm_body<1,DIMN,DIMN>(ltid, half, j % 64, j / 64, 0, As_, Bs_, rd_,
                               nullptr, W1_w, W2_w, Wf2_w, batt, Wf2_b, x, emb, cptr);
    gbar(NBLK*2);

    // P2: attn (512 jobs, block-wide)
    for (int j = bid; j < 512; j += NBLK)
        attn_body(j % 64, j / 64, cptr);
    gbar(NBLK*3);

    // P3: G4  (512 jobs: 64 x 4 x 2)
    for (int j = wkr; j < 512; j += 2*NBLK)
        gemm_body<2,DIMN,DIMN>(ltid, half, j % 64, (j / 64) & 3, j / 256, As_, Bs_, rd_,
                               nullptr, Wf1_w, nullptr, nullptr, nullptr, nullptr, nullptr, nullptr, cptr);
    gbar(NBLK*4);

    // P4: G5  (448 jobs: 64 x 7)
    for (int j = wkr; j < 448; j += 2*NBLK)
        gemm_body<3,D2,D2>(ltid, half, j % 64, j / 64, 0, As_, Bs_, rd_,
                           nullptr, Ws1_w, nullptr, nullptr, Ws1_b, nullptr, nullptr, nullptr, cptr);
    gbar(NBLK*5);

    // P5: G6  (448 jobs)
    for (int j = wkr; j < 448; j += 2*NBLK)
        gemm_body<4,D2,D2>(ltid, half, j % 64, j / 64, 0, As_, Bs_, rd_,
                           nullptr, Ws_w, nullptr, nullptr, Ws_b, nullptr, nullptr, nullptr, cptr);
    gbar(NBLK*6);

    // P6: final (8 jobs, block-wide)
    if (bid < BATCH)
        final_body(bid, sss, sred2, F1_w, F1_b, F2_w, F2_b, out);
}

// ======================= launch =======================
extern "C" void kernel_launch(void* const* d_in, const int* in_sizes, int n_in,
                              void* d_out, int out_size)
{
    const int*   x     = (const int*)  d_in[0];
    const float* emb   = (const float*)d_in[1];
    const float* Wh_w  = (const float*)d_in[2];
    const float* Wh_b  = (const float*)d_in[3];
    const float* W1_w  = (const float*)d_in[4];
    const float* W2_w  = (const float*)d_in[5];
    const float* batt  = (const float*)d_in[6];
    const float* cptr  = (const float*)d_in[7];
    const float* Wf1_w = (const float*)d_in[8];
    const float* Wf2_w = (const float*)d_in[9];
    const float* Wf2_b = (const float*)d_in[10];
    const float* Ws1_w = (const float*)d_in[11];
    const float* Ws1_b = (const float*)d_in[12];
    const float* Ws_w  = (const float*)d_in[13];
    const float* Ws_b  = (const float*)d_in[14];
    const float* F1_w  = (const float*)d_in[15];
    const float* F1_b  = (const float*)d_in[16];
    const float* F2_w  = (const float*)d_in[17];
    const float* F2_b  = (const float*)d_in[18];
    float* out = (float*)d_out;

    reset_kernel<<<1, 1>>>();
    mega_kernel<<<NBLK, 256>>>(x, emb, Wh_w, Wh_b, W1_w, W2_w, batt, cptr,
                               Wf1_w, Wf2_w, Wf2_b, Ws1_w, Ws1_b, Ws_w, Ws_b,
                               F1_w, F1_b, F2_w, F2_b, out);
}

// round 14
// speedup vs baseline: 1.3965x; 1.3965x over previous
#include <cuda_runtime.h>
#include <cuda_fp16.h>

#define DIMN   200
#define LEN    256
#define BATCH  8
#define NTOK   (BATCH*LEN)      // 2048
#define D2     (2*DIMN)         // 400

// ---------------- scratch (static device memory; no allocations) ----------------
__device__ float  g_h    [NTOK*DIMN + 64];
__device__ float  g_h1m  [NTOK*DIMN + 64];
__device__ float2 g_hpack[NTOK*DIMN + 64];
__device__ float  g_hf2c [NTOK*DIMN];
__device__ float  g_sfw  [NTOK*DIMN];
__device__ float  g_sbw  [NTOK*DIMN];
__device__ float  g_hsumP[64*DIMN + 64];
__device__ float  g_uu   [NTOK*D2];
__device__ float  g_tmp  [NTOK*D2];
__device__ float  g_part2[64*D2];

__device__ __forceinline__ float eluf(float a){ return a > 0.0f ? a : expm1f(a); }
__device__ __forceinline__ __half2 hw_tanh2(__half2 x){
    __half2 y; asm("tanh.approx.f16x2 %0, %1;" : "=r"(*(unsigned*)&y) : "r"(*(unsigned*)&x)); return y;
}
__device__ __forceinline__ __half2 hw_ex22(__half2 x){
    __half2 y; asm("ex2.approx.f16x2 %0, %1;" : "=r"(*(unsigned*)&y) : "r"(*(unsigned*)&x)); return y;
}
__device__ __forceinline__ unsigned long long pk2(float lo, float hi){
    unsigned long long r; asm("mov.b64 %0, {%1,%2};" : "=l"(r) : "f"(lo), "f"(hi)); return r;
}
__device__ __forceinline__ void fma2(unsigned long long& c, unsigned long long a, unsigned long long b){
    asm("fma.rn.f32x2 %0, %1, %2, %0;" : "+l"(c) : "l"(a), "l"(b));
}
__device__ __forceinline__ void unpk2(float& lo, float& hi, unsigned long long v){
    asm("mov.b64 {%0,%1}, %2;" : "=f"(lo), "=f"(hi) : "l"(v));
}
__device__ __forceinline__ unsigned smem_u32(const void* p){
    unsigned r; asm("{.reg .u64 t; cvta.to.shared.u64 t, %1; cvt.u32.u64 %0, t;}" : "=r"(r) : "l"(p)); return r;
}
__device__ __forceinline__ void cpa16(unsigned d, const void* s, int sz){
    asm volatile("cp.async.cg.shared.global [%0], [%1], 16, %2;" :: "r"(d), "l"(s), "r"(sz));
}
__device__ __forceinline__ void cpa_commit(){ asm volatile("cp.async.commit_group;"); }
__device__ __forceinline__ void cpa_wait1(){ asm volatile("cp.async.wait_group 1;"); }

// ==== Tiled SGEMM (BM=32, BN=64, BK=16, 128 thr, 4x4 microtile, FFMA2,
//      3-stage cp.async ring; A stored [m][k] (+4 pad), B stored [k][n]) ====
// MODE 0: h   = elu(gather(emb,x) @ Wh + Wh_b)                      -> g_h
// MODE 1: y<12: {W1(+batt,mask,/c), W2(mask,/c,pack h), Wf2(+b)};  y==12: hsum partials
// MODE 2: f = sigmoid(s_dir @ Wf1 + hf2c); uu = f*h+(1-f)*s         -> g_uu (dir=blockIdx.z)
// MODE 3: tmp = elu(uu @ Ws1 + Ws1_b)                               -> g_tmp
// MODE 4: att_s = tmp @ Ws + Ws_b; partial s_s = sum_rows uu*att_s  -> g_part2
#define BM 32
#define BN 64
#define BK 16
#define AKP (BK + 4)      // padded A row stride (conflict-free LDS.128)

template<int MODE, int K, int N>
__global__ void __launch_bounds__(128) gemm_k(
    const float* __restrict__ A,
    const float* __restrict__ B0, const float* __restrict__ B1, const float* __restrict__ B2,
    const float* __restrict__ bias0, const float* __restrict__ bias2,
    const int* __restrict__ xidx, const float* __restrict__ emb,
    const float* __restrict__ cptr)
{
    const int tid = threadIdx.x;
    const int t0  = blockIdx.x * BM;

    // ---- hsum side-channel slice (MODE 1, y==12) ----
    if (MODE == 1 && blockIdx.y == 12) {
        for (int e = tid; e < DIMN; e += 128) {
            float s = 0.0f;
            #pragma unroll 4
            for (int j = 0; j < BM; ++j) s += g_h[(t0 + j)*DIMN + e];
            g_hsumP[blockIdx.x*DIMN + e] = s;
        }
        return;
    }

    __shared__ __align__(16) float As2[3][BM][AKP];
    __shared__ __align__(16) float Bs [3][BK][BN];
    __shared__ __align__(16) float red[8][BN];

    const int tx = tid & 15;
    const int ty = tid >> 4;

    int n0, matid = 0;
    const float* B = B0;
    if (MODE == 1) {
        matid = blockIdx.y >> 2;
        n0 = (blockIdx.y & 3) * BN;
        B  = (matid == 0) ? B0 : (matid == 1) ? B1 : B2;
    } else {
        n0 = blockIdx.y * BN;
    }

    const float* Asrc;
    if      (MODE == 0) Asrc = A;
    else if (MODE == 1) Asrc = g_h;
    else if (MODE == 2) Asrc = blockIdx.z ? g_sbw : g_sfw;
    else if (MODE == 3) Asrc = g_uu;
    else                Asrc = g_tmp;

    // cp.async maps: A 32x16 (1x16B/thread), B 16x64 (2x16B/thread)
    const int am = tid >> 2;            // 0..31
    const int ak = (tid & 3) * 4;       // 0,4,8,12
    const int bk = tid >> 4;            // 0..7 (+8)
    const int bn = (tid & 15) * 4;      // 0..60

    long arow;
    if (MODE == 0) arow = (long)__ldg(&xidx[t0 + am]) * K;
    else           arow = (long)(t0 + am) * K;

    const int gn_b = n0 + bn;
    const bool bvalid = (gn_b < N);

    const unsigned sa = smem_u32(&As2[0][0][0]) + ((unsigned)(am*AKP + ak))*4u;
    const unsigned sb = smem_u32(&Bs[0][0][0])  + ((unsigned)(bk*BN + bn))*4u;
    constexpr unsigned SA_STG = BM*AKP*4u;
    constexpr unsigned SB_STG = BK*BN*4u;

    auto issueTile = [&](int st, int k0) {
        int kq = k0 + ak;
        int asz = (kq < K) ? 16 : 0;
        cpa16(sa + st*SA_STG, Asrc + arow + (asz ? kq : 0), asz);
        int k1 = k0 + bk, k2 = k1 + 8;
        int bsz1 = (bvalid && k1 < K) ? 16 : 0;
        int bsz2 = (bvalid && k2 < K) ? 16 : 0;
        cpa16(sb + st*SB_STG,            B + (bsz1 ? (long)k1*N + gn_b : 0), bsz1);
        cpa16(sb + st*SB_STG + 8*BN*4u,  B + (bsz2 ? (long)k2*N + gn_b : 0), bsz2);
    };

    unsigned long long acc2[4][2];
    #pragma unroll
    for (int i = 0; i < 4; i++) { acc2[i][0] = 0ULL; acc2[i][1] = 0ULL; }

    constexpr int T = (K + BK - 1) / BK;

    issueTile(0, 0);       cpa_commit();
    if (T > 1) issueTile(1, BK);
    cpa_commit();

    int s = 0;
    for (int t = 0; t < T; t++) {
        cpa_wait1();
        __syncthreads();
        if (t + 2 < T) issueTile((s + 2) % 3, (t + 2) * BK);
        cpa_commit();

        #pragma unroll
        for (int kk4 = 0; kk4 < BK; kk4 += 4) {
            float4 ar[4], br[4];
            #pragma unroll
            for (int i = 0; i < 4; i++)
                ar[i] = *reinterpret_cast<const float4*>(&As2[s][ty*4 + i][kk4]);
            #pragma unroll
            for (int q = 0; q < 4; q++)
                br[q] = *reinterpret_cast<const float4*>(&Bs[s][kk4 + q][tx*4]);
            #pragma unroll
            for (int q = 0; q < 4; q++) {
                unsigned long long b01 = pk2(br[q].x, br[q].y);
                unsigned long long b23 = pk2(br[q].z, br[q].w);
                #pragma unroll
                for (int i = 0; i < 4; i++) {
                    float aq = reinterpret_cast<const float*>(&ar[i])[q];
                    unsigned long long ai = pk2(aq, aq);
                    fma2(acc2[i][0], ai, b01);
                    fma2(acc2[i][1], ai, b23);
                }
            }
        }
        s = (s + 1 == 3) ? 0 : s + 1;
    }

    float acc[4][4];
    #pragma unroll
    for (int i = 0; i < 4; i++) {
        unpk2(acc[i][0], acc[i][1], acc2[i][0]);
        unpk2(acc[i][2], acc[i][3], acc2[i][1]);
    }

    // ---------------- epilogues (unchanged, validated) ----------------
    int  gcv[4]; bool ok[4]; float bj[4];
    #pragma unroll
    for (int j = 0; j < 4; j++) {
        gcv[j] = n0 + tx*4 + j;
        ok[j]  = gcv[j] < N;
    }

    if (MODE == 0) {
        #pragma unroll
        for (int j = 0; j < 4; j++) bj[j] = ok[j] ? __ldg(&bias0[gcv[j]]) : 0.0f;
        #pragma unroll
        for (int i = 0; i < 4; i++) {
            int gt = t0 + ty*4 + i;
            #pragma unroll
            for (int j = 0; j < 4; j++)
                if (ok[j]) g_h[gt*DIMN + gcv[j]] = eluf(acc[i][j] + bj[j]);
        }
    }
    else if (MODE == 1) {
        const float invc = 1.0f / __ldg(cptr);
        #pragma unroll
        for (int j = 0; j < 4; j++) {
            bj[j] = 0.0f;
            if (ok[j]) {
                if (matid == 0) bj[j] = __ldg(&bias0[gcv[j]]);
                if (matid == 2) bj[j] = __ldg(&bias2[gcv[j]]);
            }
        }
        #pragma unroll
        for (int i = 0; i < 4; i++) {
            int gt = t0 + ty*4 + i;
            long eoff = (long)__ldg(&xidx[gt]) * DIMN;
            #pragma unroll
            for (int j = 0; j < 4; j++) {
                if (!ok[j]) continue;
                if (matid == 0) {
                    bool mk = (__ldg(&emb[eoff + gcv[j]]) == 1.0f);
                    g_h1m[gt*DIMN + gcv[j]] = mk ? 1e30f : (acc[i][j] + bj[j]) * invc;
                } else if (matid == 1) {
                    bool mk = (__ldg(&emb[eoff + gcv[j]]) == 1.0f);
                    float2 pp;
                    pp.x = mk ? 1e30f : acc[i][j] * invc;
                    pp.y = g_h[gt*DIMN + gcv[j]];
                    g_hpack[gt*DIMN + gcv[j]] = pp;
                } else {
                    g_hf2c[gt*DIMN + gcv[j]] = acc[i][j] + bj[j];
                }
            }
        }
    }
    else if (MODE == 2) {
        const int dir = blockIdx.z;
        #pragma unroll
        for (int i = 0; i < 4; i++) {
            int gt = t0 + ty*4 + i;
            #pragma unroll
            for (int j = 0; j < 4; j++) {
                if (!ok[j]) continue;
                int idx = gt*DIMN + gcv[j];
                float f = 1.0f / (1.0f + __expf(-(acc[i][j] + g_hf2c[idx])));
                float hh = g_h[idx];
                float ss = Asrc[idx];
                g_uu[gt*D2 + dir*DIMN + gcv[j]] = f*hh + (1.0f - f)*ss;
            }
        }
    }
    else if (MODE == 3) {
        #pragma unroll
        for (int j = 0; j < 4; j++) bj[j] = ok[j] ? __ldg(&bias0[gcv[j]]) : 0.0f;
        #pragma unroll
        for (int i = 0; i < 4; i++) {
            int gt = t0 + ty*4 + i;
            #pragma unroll
            for (int j = 0; j < 4; j++)
                if (ok[j]) g_tmp[gt*D2 + gcv[j]] = eluf(acc[i][j] + bj[j]);
        }
    }
    else { // MODE 4
        #pragma unroll
        for (int j = 0; j < 4; j++) bj[j] = ok[j] ? __ldg(&bias0[gcv[j]]) : 0.0f;
        float pr[4] = {0,0,0,0};
        #pragma unroll
        for (int i = 0; i < 4; i++) {
            int gt = t0 + ty*4 + i;
            #pragma unroll
            for (int j = 0; j < 4; j++) {
                if (!ok[j]) continue;
                float att = acc[i][j] + bj[j];
                pr[j] += g_uu[gt*D2 + gcv[j]] * att;
            }
        }
        __syncthreads();
        #pragma unroll
        for (int j = 0; j < 4; j++) red[ty][tx*4 + j] = pr[j];
        __syncthreads();
        if (tid < BN) {
            float s2 = 0.0f;
            #pragma unroll
            for (int r = 0; r < 8; r++) s2 += red[r][tid];
            int gc = n0 + tid;
            if (gc < N) g_part2[blockIdx.x*D2 + gc] = s2;
        }
    }
}

// ======================= fused masked per-feature softmax attention ============
__global__ void __launch_bounds__(224) attn_kernel(const float* __restrict__ cptr)
{
    const int b  = blockIdx.y;
    const int l0 = blockIdx.x * 4;
    const int e  = threadIdx.x;

    const float C  = __ldg(cptr);
    const float ktf = C * 1.4426950408889634f;
    const __half2 kt2 = __float2half2_rn(ktf);

    float h1s[4];
    #pragma unroll
    for (int i = 0; i < 4; i++) h1s[i] = g_h1m[(b*LEN + l0 + i)*DIMN + e];

    float denf[4] = {0,0,0,0}, numf[4] = {0,0,0,0};
    float denb[4] = {0,0,0,0}, numb[4] = {0,0,0,0};

    const float2* __restrict__ hp = g_hpack + (size_t)b*LEN*DIMN + e;

    #pragma unroll 2
    for (int m = 0; m < l0; ++m) {
        float2 pv = __ldg(hp + m*DIMN);
        float zc[4];
        #pragma unroll
        for (int i = 0; i < 4; i++) zc[i] = h1s[i] + pv.x;
        __half2 wa = hw_ex22(__hmul2(hw_tanh2(__floats2half2_rn(zc[0], zc[1])), kt2));
        __half2 wb = hw_ex22(__hmul2(hw_tanh2(__floats2half2_rn(zc[2], zc[3])), kt2));
        float2 w01 = __half22float2(wa), w23 = __half22float2(wb);
        float w[4] = {w01.x, w01.y, w23.x, w23.y};
        #pragma unroll
        for (int i = 0; i < 4; i++) {
            float wi = (zc[i] < 1e29f) ? w[i] : 0.0f;
            denb[i] += wi;
            numb[i] = fmaf(wi, pv.y, numb[i]);
        }
    }
    #pragma unroll
    for (int i2 = 0; i2 < 4; i2++) {
        float2 pv = __ldg(hp + (l0 + i2)*DIMN);
        float zc[4];
        #pragma unroll
        for (int i = 0; i < 4; i++) zc[i] = h1s[i] + pv.x;
        __half2 wa = hw_ex22(__hmul2(hw_tanh2(__floats2half2_rn(zc[0], zc[1])), kt2));
        __half2 wb = hw_ex22(__hmul2(hw_tanh2(__floats2half2_rn(zc[2], zc[3])), kt2));
        float2 w01 = __half22float2(wa), w23 = __half22float2(wb);
        float w[4] = {w01.x, w01.y, w23.x, w23.y};
        #pragma unroll
        for (int i = 0; i < 4; i++) {
            if (i == i2) continue;
            float wi = (zc[i] < 1e29f) ? w[i] : 0.0f;
            if (i < i2) { denf[i] += wi; numf[i] = fmaf(wi, pv.y, numf[i]); }
            else        { denb[i] += wi; numb[i] = fmaf(wi, pv.y, numb[i]); }
        }
    }
    #pragma unroll 2
    for (int m = l0 + 4; m < LEN; ++m) {
        float2 pv = __ldg(hp + m*DIMN);
        float zc[4];
        #pragma unroll
        for (int i = 0; i < 4; i++) zc[i] = h1s[i] + pv.x;
        __half2 wa = hw_ex22(__hmul2(hw_tanh2(__floats2half2_rn(zc[0], zc[1])), kt2));
        __half2 wb = hw_ex22(__hmul2(hw_tanh2(__floats2half2_rn(zc[2], zc[3])), kt2));
        float2 w01 = __half22float2(wa), w23 = __half22float2(wb);
        float w[4] = {w01.x, w01.y, w23.x, w23.y};
        #pragma unroll
        for (int i = 0; i < 4; i++) {
            float wi = (zc[i] < 1e29f) ? w[i] : 0.0f;
            denf[i] += wi;
            numf[i] = fmaf(wi, pv.y, numf[i]);
        }
    }

    if (e < DIMN) {
        float hs = 0.0f;
        #pragma unroll
        for (int t = 0; t < 8; t++) hs += g_hsumP[(b*8 + t)*DIMN + e];
        hs *= 0.00390625f;
        #pragma unroll
        for (int i = 0; i < 4; i++) {
            int idx = (b*LEN + l0 + i)*DIMN + e;
            g_sfw[idx] = (denf[i] > 0.0f) ? __fdividef(numf[i], denf[i]) : hs;
            g_sbw[idx] = (denb[i] > 0.0f) ? __fdividef(numb[i], denb[i]) : hs;
        }
    }
}

// ======================= final: reduce partials + MLP (one block per batch) ====
__global__ void __launch_bounds__(256) final_kernel(
    const float* __restrict__ F1_w, const float* __restrict__ F1_b,
    const float* __restrict__ F2_w, const float* __restrict__ F2_b,
    float* __restrict__ out)
{
    __shared__ float ss[D2];
    __shared__ float red[256];
    const int b   = blockIdx.x;
    const int tid = threadIdx.x;

    for (int e = tid; e < D2; e += 256) {
        float s = 0.0f;
        #pragma unroll
        for (int mt = 0; mt < 8; ++mt)
            s += g_part2[(b*8 + mt)*D2 + e];
        ss[e] = s;
    }
    __syncthreads();

    float v = 0.0f;
    if (tid < DIMN) {
        float acc = F1_b[tid];
        #pragma unroll 4
        for (int k = 0; k < D2; ++k)
            acc = fmaf(ss[k], F1_w[k*DIMN + tid], acc);
        acc = fmaxf(acc, 0.0f);
        v = acc * F2_w[tid];
    }
    red[tid] = v;
    __syncthreads();
    for (int s = 128; s > 0; s >>= 1) {
        if (tid < s) red[tid] += red[tid + s];
        __syncthreads();
    }
    if (tid == 0) out[b] = red[0] + F2_b[0];
}

// ======================= launch =======================
extern "C" void kernel_launch(void* const* d_in, const int* in_sizes, int n_in,
                              void* d_out, int out_size)
{
    const int*   x     = (const int*)  d_in[0];
    const float* emb   = (const float*)d_in[1];
    const float* Wh_w  = (const float*)d_in[2];
    const float* Wh_b  = (const float*)d_in[3];
    const float* W1_w  = (const float*)d_in[4];
    const float* W2_w  = (const float*)d_in[5];
    const float* batt  = (const float*)d_in[6];
    const float* cptr  = (const float*)d_in[7];
    const float* Wf1_w = (const float*)d_in[8];
    const float* Wf2_w = (const float*)d_in[9];
    const float* Wf2_b = (const float*)d_in[10];
    const float* Ws1_w = (const float*)d_in[11];
    const float* Ws1_b = (const float*)d_in[12];
    const float* Ws_w  = (const float*)d_in[13];
    const float* Ws_b  = (const float*)d_in[14];
    const float* F1_w  = (const float*)d_in[15];
    const float* F1_b  = (const float*)d_in[16];
    const float* F2_w  = (const float*)d_in[17];
    const float* F2_b  = (const float*)d_in[18];
    float* out = (float*)d_out;

    gemm_k<0,DIMN,DIMN><<<dim3(NTOK/BM, 4), 128>>>(emb, Wh_w, nullptr, nullptr,
                                                   Wh_b, nullptr, x, emb, cptr);
    gemm_k<1,DIMN,DIMN><<<dim3(NTOK/BM, 13), 128>>>(nullptr, W1_w, W2_w, Wf2_w,
                                                    batt, Wf2_b, x, emb, cptr);
    attn_kernel<<<dim3(LEN/4, BATCH), 224>>>(cptr);
    gemm_k<2,DIMN,DIMN><<<dim3(NTOK/BM, 4, 2), 128>>>(nullptr, Wf1_w, nullptr, nullptr,
                                                      nullptr, nullptr, nullptr, nullptr, cptr);
    gemm_k<3,D2,D2><<<dim3(NTOK/BM, 7), 128>>>(nullptr, Ws1_w, nullptr, nullptr,
                                               Ws1_b, nullptr, nullptr, nullptr, cptr);
    gemm_k<4,D2,D2><<<dim3(NTOK/BM, 7), 128>>>(nullptr, Ws_w, nullptr, nullptr,
                                               Ws_b, nullptr, nullptr, nullptr, cptr);
    final_kernel<<<BATCH, 256>>>(F1_w, F1_b, F2_w, F2_b, out);
}